// round 10
// baseline (speedup 1.0000x reference)
#include <cuda_runtime.h>
#include <cuda_fp16.h>

#define B_ 512
#define S_ 168
#define F_ 12
#define H_ 128
#define O_ 3
#define S2_ (S_ * S_)

typedef unsigned int u32;

// ---------------- device scratch ----------------
__device__ uint4 g_W0f[16 * 9 * 32];    // L0 fragments [tile][ks][lane] (K=144: x|pad|h)
__device__ uint4 g_W1f[16 * 16 * 32];   // L1 fragments
__device__ uint4 g_Hf[24 * 16 * 32];    // head fragments [ff1 | ff2 | gate]
__device__ float g_bh[384];             // merged head bias
__device__ float g_T[3 * S2_];
__device__ float g_WfT[3 * S2_];
__device__ float g_mean[B_ * F_];
__device__ float g_x1[B_ * S_ * F_];
__device__ float g_x2[B_ * S_ * O_];
__device__ float g_x3[B_ * S_ * O_];
__device__ float g_hs[B_ * S_ * H_];

// ---------------- helpers ----------------
__device__ __forceinline__ float tanh_ap(float x) {
    float y;
    asm("tanh.approx.f32 %0, %1;" : "=f"(y) : "f"(x));
    return y;
}
__device__ __forceinline__ float siluf(float x) {
    return x * fmaf(0.5f, tanh_ap(0.5f * x), 0.5f);
}
__device__ __forceinline__ float sigf(float x) {
    return fmaf(0.5f, tanh_ap(0.5f * x), 0.5f);
}
__device__ __forceinline__ u32 hpack(float a, float b) {
    __half2 h = __floats2half2_rn(a, b);
    return *reinterpret_cast<u32*>(&h);
}
__device__ __forceinline__ void mma16816(float* d, uint4 A, u32 b0, u32 b1) {
    asm volatile(
        "mma.sync.aligned.m16n8k16.row.col.f32.f16.f16.f32 "
        "{%0,%1,%2,%3},{%4,%5,%6,%7},{%8,%9},{%0,%1,%2,%3};"
        : "+f"(d[0]), "+f"(d[1]), "+f"(d[2]), "+f"(d[3])
        : "r"(A.x), "r"(A.y), "r"(A.z), "r"(A.w), "r"(b0), "r"(b1));
}
#define CLUSTER_SYNC() do { \
    asm volatile("barrier.cluster.arrive.aligned;" ::: "memory"); \
    asm volatile("barrier.cluster.wait.aligned;" ::: "memory"); } while (0)

__device__ __forceinline__ void sts_r16(u32 a, __half v) {
    asm volatile("st.shared::cluster.b16 [%0], %1;" :: "r"(a), "h"(__half_as_ushort(v)));
}
__device__ __forceinline__ void mbar_init(u32 a, u32 cnt) {
    asm volatile("mbarrier.init.shared.b64 [%0], %1;" :: "r"(a), "r"(cnt) : "memory");
}
__device__ __forceinline__ void mbar_arrive_remote(u32 a) {
    asm volatile("mbarrier.arrive.release.cluster.shared::cluster.b64 _, [%0];" :: "r"(a) : "memory");
}
__device__ __forceinline__ void mbar_wait(u32 a, u32 parity) {
    asm volatile(
        "{\n\t.reg .pred P;\n"
        "W%=:\n\t"
        "mbarrier.try_wait.parity.acquire.cluster.shared::cta.b64 P, [%0], %1, 0x989680;\n\t"
        "@P bra D%=;\n\t"
        "bra W%=;\n"
        "D%=:\n\t}"
        :: "r"(a), "r"(parity) : "memory");
}

// weight element accessors
// L0 K layout: k in [0,12) -> x, [12,16) -> zero pad, [16,144) -> h[k-16]
__device__ __forceinline__ float w0_at(const float* W, int o, int k) {
    if (k < 12)  return W[o * 140 + k];
    if (k < 16)  return 0.f;
    return W[o * 140 + (k - 4)];
}
// head plain ordering: rows [0,128)=ff1, [128,256)=ff2, [256,384)=ta+tb
__device__ __forceinline__ float wh_at(const float* f1, const float* f2,
                                       const float* ta, const float* tb, int m, int k) {
    if (m < 128) return f1[m * 256 + k];
    if (m < 256) return f2[(m - 128) * 256 + k];
    return ta[(m - 256) * 256 + k] + tb[(m - 256) * 256 + k];
}

// ---------------- fragment precompute ----------------
__global__ void k_prep(const float* __restrict__ Wb0, const float* __restrict__ Wb1,
                       const float* __restrict__ Wff1, const float* __restrict__ Wff2,
                       const float* __restrict__ Wta, const float* __restrict__ Wtb,
                       const float* __restrict__ bff1, const float* __restrict__ bff2,
                       const float* __restrict__ bta, const float* __restrict__ btb) {
    int idx = blockIdx.x * blockDim.x + threadIdx.x;
    const int N0 = 16 * 9 * 32, N1 = 16 * 16 * 32, NH = 24 * 16 * 32;
    if (idx < N0 + N1 + NH) {
        int which, tile, ks, l, i = idx;
        if (i < N0)           { which = 0; tile = i / (9 * 32);  ks = (i / 32) % 9; }
        else if (i < N0 + N1) { which = 1; i -= N0; tile = i / (16 * 32); ks = (i / 32) % 16; }
        else                  { which = 2; i -= N0 + N1; tile = i / (16 * 32); ks = (i / 32) % 16; }
        l = i % 32;
        int g = l / 4, ti = l % 4;
        int r0 = tile * 16 + g, k0 = ks * 16 + ti * 2;
        float e[4][2];
        for (int half = 0; half < 2; half++) {
            for (int rr = 0; rr < 2; rr++) {
                for (int cc = 0; cc < 2; cc++) {
                    int o = r0 + rr * 8, k = k0 + half * 8 + cc;
                    float wv;
                    if (which == 0)      wv = w0_at(Wb0, o, k);
                    else if (which == 1) wv = Wb1[o * 256 + k];
                    else                 wv = wh_at(Wff1, Wff2, Wta, Wtb, o, k);
                    e[half * 2 + rr][cc] = wv;
                }
            }
        }
        uint4 out;
        out.x = hpack(e[0][0], e[0][1]);
        out.y = hpack(e[1][0], e[1][1]);
        out.z = hpack(e[2][0], e[2][1]);
        out.w = hpack(e[3][0], e[3][1]);
        if (which == 0)      g_W0f[idx] = out;
        else if (which == 1) g_W1f[idx - N0] = out;
        else                 g_Hf[idx - N0 - N1] = out;
    } else if (idx < N0 + N1 + NH + 384) {
        int j = idx - N0 - N1 - NH;
        float b;
        if (j < 128)      b = bff1[j];
        else if (j < 256) b = bff2[j - 128];
        else              b = bta[j - 256] + btb[j - 256];
        g_bh[j] = b;
    }
}

// ---------------- collapsed _sff operators (transposed) ----------------
__device__ __forceinline__ float sff_contrib(const float* __restrict__ conv,
                                             const float* __restrict__ lin,
                                             int p, int seg, int pad, int so, int si) {
    int phase = so % p, q = so / p;
    float acc = 0.f;
    for (int kk = 0; kk < seg; ++kk) {
        int d = si - (kk * p + phase);
        float c = 0.f;
        if (d >= -pad && d <= pad) c = conv[d + pad];
        if (d == 0) c += 1.f;
        acc += lin[q * seg + kk] * c;
    }
    return acc;
}

__global__ void k_build_T(const float* __restrict__ c3, const float* __restrict__ l3,
                          const float* __restrict__ c6, const float* __restrict__ l6,
                          const float* __restrict__ c12, const float* __restrict__ l12,
                          const float* __restrict__ c24, const float* __restrict__ l24) {
    int idx = blockIdx.x * blockDim.x + threadIdx.x;
    if (idx >= 3 * S2_) return;
    int L = idx / S2_, r = idx % S2_;
    int so = r / S_, si = r % S_;
    float a = sff_contrib(c3 + L * 3, l3 + L * 56 * 56, 3, 56, 1, so, si)
            + sff_contrib(c6 + L * 7, l6 + L * 28 * 28, 6, 28, 3, so, si)
            + sff_contrib(c12 + L * 13, l12 + L * 14 * 14, 12, 14, 6, so, si)
            + sff_contrib(c24 + L * 25, l24 + L * 7 * 7, 24, 7, 12, so, si);
    g_T[L * S2_ + si * S_ + so] = 0.25f * a;
}

__global__ void k_twf(const float* __restrict__ Wfits) {
    int idx = blockIdx.x * blockDim.x + threadIdx.x;
    if (idx >= 3 * S2_) return;
    int c = idx / S2_, r = idx % S2_;
    int s = r / S_, p = r % S_;
    g_WfT[c * S2_ + s * S_ + p] = Wfits[c * S2_ + p * S_ + s];
}

__global__ void k_mean(const float* __restrict__ x) {
    int w = (blockIdx.x * blockDim.x + threadIdx.x) >> 5;
    int lane = threadIdx.x & 31;
    if (w >= B_ * F_) return;
    const float* p = x + w * S_;
    float s = 0.f;
    for (int i = lane; i < S_; i += 32) s += p[i];
#pragma unroll
    for (int o = 16; o; o >>= 1) s += __shfl_xor_sync(0xffffffffu, s, o);
    if (!lane) g_mean[w] = s * (1.f / (float)S_);
}

// ---------------- fused front ----------------
__global__ void k_front(const float* __restrict__ x) {
    __shared__ float xs[S_][F_];
    __shared__ float x1s[S_][4];
    int b = blockIdx.x, t = threadIdx.x;
    for (int i = t; i < S_ * F_; i += blockDim.x) {
        int si = i / F_, f = i % F_;
        xs[si][f] = x[b * F_ * S_ + f * S_ + si] - g_mean[b * F_ + f];
    }
    __syncthreads();
    if (t < S_) {
        float acc[F_];
#pragma unroll
        for (int f = 0; f < F_; f++) acc[f] = 0.f;
        for (int si = 0; si < S_; ++si) {
            float tw = g_T[si * S_ + t];
#pragma unroll
            for (int f = 0; f < F_; f++) acc[f] = fmaf(tw, xs[si][f], acc[f]);
        }
        float* o = g_x1 + (b * S_ + t) * F_;
#pragma unroll
        for (int f = 0; f < F_; f++) o[f] = acc[f];
        x1s[t][0] = acc[0]; x1s[t][1] = acc[1]; x1s[t][2] = acc[2];
    }
    __syncthreads();
    if (t < S_) {
        float a2[3] = {0.f, 0.f, 0.f}, a3[3] = {0.f, 0.f, 0.f};
        for (int si = 0; si < S_; ++si) {
            float t1 = g_T[S2_ + si * S_ + t];
            float t2 = g_T[2 * S2_ + si * S_ + t];
#pragma unroll
            for (int c = 0; c < 3; c++) {
                a2[c] = fmaf(t1, x1s[si][c], a2[c]);
                a3[c] = fmaf(t2, x1s[si][c], a3[c]);
            }
        }
#pragma unroll
        for (int c = 0; c < 3; c++) {
            g_x2[(b * S_ + t) * 3 + c] = a2[c];
            g_x3[(b * S_ + t) * 3 + c] = a3[c];
        }
    }
}

// ---------------- CfC recurrence: layer-pipelined cluster, 2 groups ----------
// Cluster = 2 CTAs, 16 rows (2 groups x 8).
// CTA0: W0+W1 in SMEM; computes L0->L1 per group, pushes zb to CTA1.
// CTA1: head in SMEM (warp w owns tiles {w,8+w,16+w} -> register-local combine),
//       pushes h back to CTA0's in buffer.
// SMEM (bytes):
//   [0,16)       mb[2]  (one signal barrier per group)
//   [64, ...)    weights: CTA0 sW0(73728)+sW1(131072); CTA1 sHf(196608)
//   [204864,...) acts:
//     CTA0: in0[2][8][168]h (5376) | za[8][264]h (4224) | sb0(1024) | sb1(1024)
//     CTA1: zbuf[2][8][264]h (8448) | sbh(1536)
#define ACT_OFF 204864
__global__ void __launch_bounds__(256, 1) __cluster_dims__(2, 1, 1)
k_rnn(const float* __restrict__ bb0, const float* __restrict__ bb1) {
    extern __shared__ __align__(16) char s[];
    const int t = threadIdx.x, w = t >> 5, l = t & 31, g = l >> 4 ? 0 : 0, dummy = 0;
    (void)g; (void)dummy;
    const int gg = (l >> 2), ti = l & 3;
    u32 rank;
    asm("mov.u32 %0, %%cluster_ctarank;" : "=r"(rank));
    const u32 peer = rank ^ 1u;
    const int bb = (blockIdx.x >> 1) * 16;

    u32 base;
    asm("{ .reg .u64 a; cvta.to.shared.u64 a, %1; cvt.u32.u64 %0, a; }" : "=r"(base) : "l"(s));
    u32 mb0 = base, mb1 = base + 8;
    u32 mb0_r, mb1_r, act_r;
    asm("mapa.shared::cluster.u32 %0, %1, %2;" : "=r"(mb0_r) : "r"(mb0), "r"(peer));
    asm("mapa.shared::cluster.u32 %0, %1, %2;" : "=r"(mb1_r) : "r"(mb1), "r"(peer));
    asm("mapa.shared::cluster.u32 %0, %1, %2;" : "=r"(act_r) : "r"(base + ACT_OFF), "r"(peer));

    if (rank == 0) {
        // ================= producer CTA: L0 + L1 =================
        uint4*  sW0 = (uint4*)(s + 64);
        uint4*  sW1 = (uint4*)(s + 64 + 73728);
        __half* in0 = (__half*)(s + ACT_OFF);             // [2][8][168]
        __half* za  = (__half*)(s + ACT_OFF + 5376);      // [8][264]
        float*  sb0 = (float*)(s + ACT_OFF + 5376 + 4224);
        float*  sb1 = sb0 + 256;

        for (int i = t; i < 4608; i += 256) sW0[i] = g_W0f[i];
        for (int i = t; i < 8192; i += 256) sW1[i] = g_W1f[i];
        sb0[t] = bb0[t];
        sb1[t] = bb1[t];
        for (int i = t; i < 2688; i += 256) in0[i] = __float2half(0.f);
        if (t == 0) { mbar_init(mb0, 1); mbar_init(mb1, 1); }
        __syncthreads();
        CLUSTER_SYNC();
        // x(.,0)
        if (t < 192) {
            int r = t / 12, f = t - r * 12;
            in0[(r >> 3) * 1344 + (r & 7) * 168 + f] =
                __float2half(g_x1[(bb + r) * S_ * F_ + f]);
        }
        __syncthreads();

        const int t0 = 2 * w, t1 = 2 * w + 1;
        const int ra = 2 * ti, rb = 2 * ti + 1;
        const int o0 = t0 * 16 + gg, o1 = t1 * 16 + gg;

        for (int step = 0; step < S_; ++step) {
            const u32 par = step & 1u;
#pragma unroll 1
            for (int grp = 0; grp < 2; grp++) {
                mbar_wait(grp ? mb1 : mb0, par);     // h(grp,s-1) present
                __half* ing = in0 + grp * 1344;

                // ---- L0: tiles t0,t1; K=144 ----
                float d0[4], d1[4];
                d0[0] = d0[1] = sb0[o0];
                d0[2] = d0[3] = sb0[o0 + 8];
                d1[0] = d1[1] = sb0[o1];
                d1[2] = d1[3] = sb0[o1 + 8];
#pragma unroll
                for (int ks = 0; ks < 9; ks++) {
                    u32 b0 = *(const u32*)&ing[gg * 168 + ks * 16 + ti * 2];
                    u32 b1 = *(const u32*)&ing[gg * 168 + ks * 16 + ti * 2 + 8];
                    mma16816(d0, sW0[(t0 * 9 + ks) * 32 + l], b0, b1);
                    mma16816(d1, sW0[(t1 * 9 + ks) * 32 + l], b0, b1);
                }
                za[ra * 264 + o0]     = __float2half(siluf(d0[0]));
                za[rb * 264 + o0]     = __float2half(siluf(d0[1]));
                za[ra * 264 + o0 + 8] = __float2half(siluf(d0[2]));
                za[rb * 264 + o0 + 8] = __float2half(siluf(d0[3]));
                za[ra * 264 + o1]     = __float2half(siluf(d1[0]));
                za[rb * 264 + o1]     = __float2half(siluf(d1[1]));
                za[ra * 264 + o1 + 8] = __float2half(siluf(d1[2]));
                za[rb * 264 + o1 + 8] = __float2half(siluf(d1[3]));
                __syncthreads();

                // ---- L1: tiles t0,t1; K=256 ----
                d0[0] = d0[1] = sb1[o0];
                d0[2] = d0[3] = sb1[o0 + 8];
                d1[0] = d1[1] = sb1[o1];
                d1[2] = d1[3] = sb1[o1 + 8];
#pragma unroll
                for (int ks = 0; ks < 16; ks++) {
                    u32 b0 = *(const u32*)&za[gg * 264 + ks * 16 + ti * 2];
                    u32 b1 = *(const u32*)&za[gg * 264 + ks * 16 + ti * 2 + 8];
                    mma16816(d0, sW1[(t0 * 16 + ks) * 32 + l], b0, b1);
                    mma16816(d1, sW1[(t1 * 16 + ks) * 32 + l], b0, b1);
                }
                // push zb(grp) to CTA1
                {
                    u32 za_r = act_r + grp * 4224;
                    sts_r16(za_r + ra * 528 + o0 * 2,       __float2half(siluf(d0[0])));
                    sts_r16(za_r + rb * 528 + o0 * 2,       __float2half(siluf(d0[1])));
                    sts_r16(za_r + ra * 528 + (o0 + 8) * 2, __float2half(siluf(d0[2])));
                    sts_r16(za_r + rb * 528 + (o0 + 8) * 2, __float2half(siluf(d0[3])));
                    sts_r16(za_r + ra * 528 + o1 * 2,       __float2half(siluf(d1[0])));
                    sts_r16(za_r + rb * 528 + o1 * 2,       __float2half(siluf(d1[1])));
                    sts_r16(za_r + ra * 528 + (o1 + 8) * 2, __float2half(siluf(d1[2])));
                    sts_r16(za_r + rb * 528 + (o1 + 8) * 2, __float2half(siluf(d1[3])));
                }
                __syncthreads();
                if (t == 0) mbar_arrive_remote(grp ? mb1_r : mb0_r);
                // x(grp, s+1)
                if (step + 1 < S_ && t < 96) {
                    int r = t / 12, f = t - r * 12;
                    ing[r * 168 + f] =
                        __float2half(g_x1[((bb + grp * 8 + r) * S_ + step + 1) * F_ + f]);
                }
            }
        }
        CLUSTER_SYNC();
    } else {
        // ================= consumer CTA: head + combine =================
        uint4*  sHf  = (uint4*)(s + 64);
        __half* zbuf = (__half*)(s + ACT_OFF);            // [2][8][264]
        float*  sbh  = (float*)(s + ACT_OFF + 8448);

        for (int i = t; i < 12288; i += 256) sHf[i] = g_Hf[i];
        for (int i = t; i < 384; i += 256) sbh[i] = g_bh[i];
        if (t == 0) { mbar_init(mb0, 1); mbar_init(mb1, 1); }
        __syncthreads();
        CLUSTER_SYNC();
        if (t == 0) { mbar_arrive_remote(mb0_r); mbar_arrive_remote(mb1_r); }  // h(-1)=0 seeded

        const int t0 = w, t1 = 8 + w, t2 = 16 + w;    // ff1/ff2/gate tiles, same 16 outputs
        const int ob = w * 16;                         // h-output base

        for (int step = 0; step < S_; ++step) {
            const u32 par = step & 1u;
#pragma unroll 1
            for (int grp = 0; grp < 2; grp++) {
                mbar_wait(grp ? mb1 : mb0, par);      // zb(grp,s) present
                __half* zg = zbuf + grp * 2112;

                float e0[4], e1[4], e2[4];
                e0[0] = e0[1] = sbh[t0 * 16 + gg];
                e0[2] = e0[3] = sbh[t0 * 16 + gg + 8];
                e1[0] = e1[1] = sbh[t1 * 16 + gg];
                e1[2] = e1[3] = sbh[t1 * 16 + gg + 8];
                e2[0] = e2[1] = sbh[t2 * 16 + gg];
                e2[2] = e2[3] = sbh[t2 * 16 + gg + 8];
#pragma unroll
                for (int ks = 0; ks < 16; ks++) {
                    u32 b0 = *(const u32*)&zg[gg * 264 + ks * 16 + ti * 2];
                    u32 b1 = *(const u32*)&zg[gg * 264 + ks * 16 + ti * 2 + 8];
                    mma16816(e0, sHf[(t0 * 16 + ks) * 32 + l], b0, b1);
                    mma16816(e1, sHf[(t1 * 16 + ks) * 32 + l], b0, b1);
                    mma16816(e2, sHf[(t2 * 16 + ks) * 32 + l], b0, b1);
                }
                // register-local combine + push h to CTA0 + global store
                u32 h_r = act_r + grp * 2688;
#pragma unroll
                for (int j = 0; j < 4; j++) {
                    float f1 = tanh_ap(e0[j]);
                    float f2 = tanh_ap(e1[j]);
                    float sg = sigf(e2[j]);
                    float h = f1 + sg * (f2 - f1);
                    int row = 2 * ti + (j & 1);
                    int jh = ob + gg + ((j >> 1) ? 8 : 0);
                    __half hh = __float2half(h);
                    sts_r16(h_r + row * 336 + (16 + jh) * 2, hh);
                    g_hs[((bb + grp * 8 + row) * S_ + step) * H_ + jh] = h;
                }
                __syncthreads();
                if (t == 0) mbar_arrive_remote(grp ? mb1_r : mb0_r);
            }
        }
        CLUSTER_SYNC();
    }
}

// ---------------- fused back ----------------
__global__ void k_back(const float* __restrict__ Wfc, const float* __restrict__ bfc,
                       float* __restrict__ out) {
    __shared__ float r1s[S_][4];
    int b = blockIdx.x, t = threadIdx.x;
    int w = t >> 5, lane = t & 31;
    for (int s = w; s < S_; s += 8) {
        const float* h = g_hs + (size_t)(b * S_ + s) * H_;
        float a0 = 0.f, a1 = 0.f, a2 = 0.f;
        for (int i = lane; i < H_; i += 32) {
            float hv = h[i];
            a0 = fmaf(hv, Wfc[i], a0);
            a1 = fmaf(hv, Wfc[H_ + i], a1);
            a2 = fmaf(hv, Wfc[2 * H_ + i], a2);
        }
#pragma unroll
        for (int o = 16; o; o >>= 1) {
            a0 += __shfl_xor_sync(0xffffffffu, a0, o);
            a1 += __shfl_xor_sync(0xffffffffu, a1, o);
            a2 += __shfl_xor_sync(0xffffffffu, a2, o);
        }
        if (!lane) {
            r1s[s][0] = a0 + bfc[0] + g_x3[(b * S_ + s) * 3 + 0];
            r1s[s][1] = a1 + bfc[1] + g_x3[(b * S_ + s) * 3 + 1];
            r1s[s][2] = a2 + bfc[2] + g_x3[(b * S_ + s) * 3 + 2];
        }
    }
    __syncthreads();
    if (t < S_) {
        float a0 = g_mean[b * F_ + 0] + g_x2[(b * S_ + t) * 3 + 0];
        float a1 = g_mean[b * F_ + 1] + g_x2[(b * S_ + t) * 3 + 1];
        float a2 = g_mean[b * F_ + 2] + g_x2[(b * S_ + t) * 3 + 2];
        for (int s = 0; s < S_; ++s) {
            a0 = fmaf(r1s[s][0], g_WfT[0 * S2_ + s * S_ + t], a0);
            a1 = fmaf(r1s[s][1], g_WfT[1 * S2_ + s * S_ + t], a1);
            a2 = fmaf(r1s[s][2], g_WfT[2 * S2_ + s * S_ + t], a2);
        }
        float* o = out + (b * S_ + t) * 3;
        o[0] = a0; o[1] = a1; o[2] = a2;
    }
}

// ---------------- launch ----------------
extern "C" void kernel_launch(void* const* d_in, const int* in_sizes, int n_in,
                              void* d_out, int out_size) {
    const float* x     = (const float*)d_in[0];
    const float* c3    = (const float*)d_in[1];
    const float* l3    = (const float*)d_in[2];
    const float* c6    = (const float*)d_in[3];
    const float* l6    = (const float*)d_in[4];
    const float* c12   = (const float*)d_in[5];
    const float* l12   = (const float*)d_in[6];
    const float* c24   = (const float*)d_in[7];
    const float* l24   = (const float*)d_in[8];
    const float* Wb0   = (const float*)d_in[9];
    const float* bb0   = (const float*)d_in[10];
    const float* Wb1   = (const float*)d_in[11];
    const float* bb1   = (const float*)d_in[12];
    const float* Wff1  = (const float*)d_in[13];
    const float* bff1  = (const float*)d_in[14];
    const float* Wff2  = (const float*)d_in[15];
    const float* bff2  = (const float*)d_in[16];
    const float* Wta   = (const float*)d_in[17];
    const float* bta   = (const float*)d_in[18];
    const float* Wtb   = (const float*)d_in[19];
    const float* btb   = (const float*)d_in[20];
    const float* Wfc   = (const float*)d_in[21];
    const float* bfc   = (const float*)d_in[22];
    const float* Wfits = (const float*)d_in[23];
    float* out = (float*)d_out;

    const int SMEM_RNN = 216512;
    cudaFuncSetAttribute(k_rnn, cudaFuncAttributeMaxDynamicSharedMemorySize, SMEM_RNN);

    const int NPREP = 16 * 9 * 32 + 16 * 16 * 32 + 24 * 16 * 32 + 384;
    k_prep<<<(NPREP + 255) / 256, 256>>>(Wb0, Wb1, Wff1, Wff2, Wta, Wtb,
                                         bff1, bff2, bta, btb);
    k_build_T<<<(3 * S2_ + 255) / 256, 256>>>(c3, l3, c6, l6, c12, l12, c24, l24);
    k_twf<<<(3 * S2_ + 255) / 256, 256>>>(Wfits);
    k_mean<<<(B_ * F_ * 32 + 255) / 256, 256>>>(x);
    k_front<<<B_, 192>>>(x);
    k_rnn<<<64, 256, SMEM_RNN>>>(bb0, bb1);
    k_back<<<B_, 256>>>(Wfc, bfc, out);
}

// round 11
// speedup vs baseline: 1.2350x; 1.2350x over previous
#include <cuda_runtime.h>
#include <cuda_fp16.h>

#define B_ 512
#define S_ 168
#define F_ 12
#define H_ 128
#define O_ 3
#define S2_ (S_ * S_)
#define ROWS 8

typedef unsigned int u32;

// ---------------- device scratch ----------------
__device__ uint4 g_W0f[16 * 9 * 32];    // L0 fragments [tile][ks][lane] (K=144: x|pad|h)
__device__ uint4 g_W1f[16 * 16 * 32];   // L1 fragments [tile][ks][lane]
__device__ uint4 g_Hf[24 * 16 * 32];    // head fragments (per-rank blocks [ff1|ff2|gate])
__device__ float g_bh[384];
__device__ float g_T[3 * S2_];
__device__ float g_WfT[3 * S2_];
__device__ float g_mean[B_ * F_];
__device__ float g_x1[B_ * S_ * F_];
__device__ float g_x2[B_ * S_ * O_];
__device__ float g_x3[B_ * S_ * O_];
__device__ float g_hs[B_ * S_ * H_];

// ---------------- helpers ----------------
__device__ __forceinline__ float tanh_ap(float x) {
    float y;
    asm("tanh.approx.f32 %0, %1;" : "=f"(y) : "f"(x));
    return y;
}
__device__ __forceinline__ float siluf(float x) {
    return x * fmaf(0.5f, tanh_ap(0.5f * x), 0.5f);
}
__device__ __forceinline__ float sigf(float x) {
    return fmaf(0.5f, tanh_ap(0.5f * x), 0.5f);
}
__device__ __forceinline__ u32 hpack(float a, float b) {
    __half2 h = __floats2half2_rn(a, b);
    return *reinterpret_cast<u32*>(&h);
}
__device__ __forceinline__ void mma16816(float* d, uint4 A, u32 b0, u32 b1) {
    asm volatile(
        "mma.sync.aligned.m16n8k16.row.col.f32.f16.f16.f32 "
        "{%0,%1,%2,%3},{%4,%5,%6,%7},{%8,%9},{%0,%1,%2,%3};"
        : "+f"(d[0]), "+f"(d[1]), "+f"(d[2]), "+f"(d[3])
        : "r"(A.x), "r"(A.y), "r"(A.z), "r"(A.w), "r"(b0), "r"(b1));
}
#define CLUSTER_SYNC() do { \
    asm volatile("barrier.cluster.arrive.aligned;" ::: "memory"); \
    asm volatile("barrier.cluster.wait.aligned;" ::: "memory"); } while (0)
#define CLUSTER_ARRIVE() asm volatile("barrier.cluster.arrive.aligned;" ::: "memory")
#define CLUSTER_WAIT()   asm volatile("barrier.cluster.wait.aligned;" ::: "memory")

__device__ __forceinline__ void sts_r16(u32 a, __half v) {
    asm volatile("st.shared::cluster.b16 [%0], %1;" :: "r"(a), "h"(__half_as_ushort(v)));
}

// weight element accessors
// L0 K layout: [0,12)=x, [12,16)=pad, [16,144)=h
__device__ __forceinline__ float w0_at(const float* W, int o, int k) {
    if (k < 12)  return W[o * 140 + k];
    if (k < 16)  return 0.f;
    return W[o * 140 + (k - 4)];
}
// head reorder: block r (192 rows) = [ff1(64r:64r+64); ff2(...); gate(...)]
__device__ __forceinline__ float wh_at(const float* f1, const float* f2,
                                       const float* ta, const float* tb, int m, int k) {
    int blk = m / 192, o = m % 192, base = blk * 64;
    if (o < 64)  return f1[(base + o) * 256 + k];
    if (o < 128) return f2[(base + o - 64) * 256 + k];
    return ta[(base + o - 128) * 256 + k] + tb[(base + o - 128) * 256 + k];
}

__device__ __forceinline__ float sff_contrib(const float* __restrict__ conv,
                                             const float* __restrict__ lin,
                                             int p, int seg, int pad, int so, int si) {
    int phase = so % p, q = so / p;
    float acc = 0.f;
    for (int kk = 0; kk < seg; ++kk) {
        int d = si - (kk * p + phase);
        float c = 0.f;
        if (d >= -pad && d <= pad) c = conv[d + pad];
        if (d == 0) c += 1.f;
        acc += lin[q * seg + kk] * c;
    }
    return acc;
}

// ---------------- merged prep: fragments + biases + T + WfT ----------------
__global__ void k_preall(const float* __restrict__ Wb0, const float* __restrict__ Wb1,
                         const float* __restrict__ Wff1, const float* __restrict__ Wff2,
                         const float* __restrict__ Wta, const float* __restrict__ Wtb,
                         const float* __restrict__ bff1, const float* __restrict__ bff2,
                         const float* __restrict__ bta, const float* __restrict__ btb,
                         const float* __restrict__ c3, const float* __restrict__ l3,
                         const float* __restrict__ c6, const float* __restrict__ l6,
                         const float* __restrict__ c12, const float* __restrict__ l12,
                         const float* __restrict__ c24, const float* __restrict__ l24,
                         const float* __restrict__ Wfits) {
    int idx = blockIdx.x * blockDim.x + threadIdx.x;
    const int N0 = 16 * 9 * 32, N1 = 16 * 16 * 32, NH = 24 * 16 * 32;
    const int NP = N0 + N1 + NH + 384;
    if (idx < N0 + N1 + NH) {
        int which, tile, ks, l, i = idx;
        if (i < N0)           { which = 0; tile = i / (9 * 32);  ks = (i / 32) % 9; }
        else if (i < N0 + N1) { which = 1; i -= N0; tile = i / (16 * 32); ks = (i / 32) % 16; }
        else                  { which = 2; i -= N0 + N1; tile = i / (16 * 32); ks = (i / 32) % 16; }
        l = i % 32;
        int g = l / 4, ti = l % 4;
        int r0 = tile * 16 + g, k0 = ks * 16 + ti * 2;
        float e[4][2];
        for (int half = 0; half < 2; half++) {
            for (int rr = 0; rr < 2; rr++) {
                for (int cc = 0; cc < 2; cc++) {
                    int o = r0 + rr * 8, k = k0 + half * 8 + cc;
                    float wv;
                    if (which == 0)      wv = w0_at(Wb0, o, k);
                    else if (which == 1) wv = Wb1[o * 256 + k];
                    else                 wv = wh_at(Wff1, Wff2, Wta, Wtb, o, k);
                    e[half * 2 + rr][cc] = wv;
                }
            }
        }
        uint4 out;
        out.x = hpack(e[0][0], e[0][1]);
        out.y = hpack(e[1][0], e[1][1]);
        out.z = hpack(e[2][0], e[2][1]);
        out.w = hpack(e[3][0], e[3][1]);
        if (which == 0)      g_W0f[idx] = out;
        else if (which == 1) g_W1f[idx - N0] = out;
        else                 g_Hf[idx - N0 - N1] = out;
    } else if (idx < NP) {
        int m = idx - N0 - N1 - NH;
        int blk = m / 192, o = m % 192, base = blk * 64;
        float b;
        if (o < 64)       b = bff1[base + o];
        else if (o < 128) b = bff2[base + o - 64];
        else              b = bta[base + o - 128] + btb[base + o - 128];
        g_bh[m] = b;
    } else if (idx < NP + 3 * S2_) {
        int j = idx - NP;
        int L = j / S2_, r = j % S2_;
        int so = r / S_, si = r % S_;
        float a = sff_contrib(c3 + L * 3, l3 + L * 56 * 56, 3, 56, 1, so, si)
                + sff_contrib(c6 + L * 7, l6 + L * 28 * 28, 6, 28, 3, so, si)
                + sff_contrib(c12 + L * 13, l12 + L * 14 * 14, 12, 14, 6, so, si)
                + sff_contrib(c24 + L * 25, l24 + L * 7 * 7, 24, 7, 12, so, si);
        g_T[L * S2_ + si * S_ + so] = 0.25f * a;
    } else if (idx < NP + 6 * S2_) {
        int j = idx - NP - 3 * S2_;
        int c = j / S2_, r = j % S2_;
        int s = r / S_, p = r % S_;
        g_WfT[c * S2_ + s * S_ + p] = Wfits[c * S2_ + p * S_ + s];
    }
}

__global__ void k_mean(const float* __restrict__ x) {
    int w = (blockIdx.x * blockDim.x + threadIdx.x) >> 5;
    int lane = threadIdx.x & 31;
    if (w >= B_ * F_) return;
    const float* p = x + w * S_;
    float s = 0.f;
    for (int i = lane; i < S_; i += 32) s += p[i];
#pragma unroll
    for (int o = 16; o; o >>= 1) s += __shfl_xor_sync(0xffffffffu, s, o);
    if (!lane) g_mean[w] = s * (1.f / (float)S_);
}

// ---------------- fused front ----------------
__global__ void k_front(const float* __restrict__ x) {
    __shared__ float xs[S_][F_];
    __shared__ float x1s[S_][4];
    int b = blockIdx.x, t = threadIdx.x;
    for (int i = t; i < S_ * F_; i += blockDim.x) {
        int si = i / F_, f = i % F_;
        xs[si][f] = x[b * F_ * S_ + f * S_ + si] - g_mean[b * F_ + f];
    }
    __syncthreads();
    if (t < S_) {
        float acc[F_];
#pragma unroll
        for (int f = 0; f < F_; f++) acc[f] = 0.f;
        for (int si = 0; si < S_; ++si) {
            float tw = g_T[si * S_ + t];
#pragma unroll
            for (int f = 0; f < F_; f++) acc[f] = fmaf(tw, xs[si][f], acc[f]);
        }
        float* o = g_x1 + (b * S_ + t) * F_;
#pragma unroll
        for (int f = 0; f < F_; f++) o[f] = acc[f];
        x1s[t][0] = acc[0]; x1s[t][1] = acc[1]; x1s[t][2] = acc[2];
    }
    __syncthreads();
    if (t < S_) {
        float a2[3] = {0.f, 0.f, 0.f}, a3[3] = {0.f, 0.f, 0.f};
        for (int si = 0; si < S_; ++si) {
            float t1 = g_T[S2_ + si * S_ + t];
            float t2 = g_T[2 * S2_ + si * S_ + t];
#pragma unroll
            for (int c = 0; c < 3; c++) {
                a2[c] = fmaf(t1, x1s[si][c], a2[c]);
                a3[c] = fmaf(t2, x1s[si][c], a3[c]);
            }
        }
#pragma unroll
        for (int c = 0; c < 3; c++) {
            g_x2[(b * S_ + t) * 3 + c] = a2[c];
            g_x3[(b * S_ + t) * 3 + c] = a3[c];
        }
    }
}

// ---------------- CfC recurrence: cluster-2, K-split L1 (2 rendezvous/step) --
// SMEM (bytes):
//   [0,36864)         sW0  (this CTA's 8 L0 tiles)
//   [36864,102400)    sW1  (ALL 16 tiles x own 8 ks)
//   [102400,200704)   sHf  (this CTA's 12 head tiles)
//   [200704,203392)   in0  [8][168]h
//   [203392,207616)   za   [8][264]h   (own 128 cols at global positions)
//   [207616,211840)   pA   [8][264]h   (own L1 partial, all 256 outs)
//   [211840,216064)   pB   [8][264]h   (peer partial, written remotely)
//   [216064,220288)   zb   [8][264]h   (full, computed redundantly)
//   [220288,226688)   hdro [8][200]f
//   [226688,227712)   sb0 | [227712,228736) sb1 | [228736,230272) sbh
__global__ void __launch_bounds__(256, 1) __cluster_dims__(2, 1, 1)
k_rnn(const float* __restrict__ bb0, const float* __restrict__ bb1) {
    extern __shared__ __align__(16) char s[];
    uint4*  sW0  = (uint4*)(s);
    uint4*  sW1  = (uint4*)(s + 36864);
    uint4*  sHf  = (uint4*)(s + 102400);
    __half* in0  = (__half*)(s + 200704);
    __half* za   = (__half*)(s + 203392);
    __half* pA   = (__half*)(s + 207616);
    __half* pB   = (__half*)(s + 211840);
    __half* zb   = (__half*)(s + 216064);
    float*  hdro = (float*)(s + 220288);
    float*  sb0  = (float*)(s + 226688);
    float*  sb1  = (float*)(s + 227712);
    float*  sbh  = (float*)(s + 228736);

    const int t = threadIdx.x, w = t >> 5, l = t & 31, gg = l >> 2, ti = l & 3;
    u32 rank;
    asm("mov.u32 %0, %%cluster_ctarank;" : "=r"(rank));
    const u32 peer = rank ^ 1u;
    const int bb = (blockIdx.x >> 1) * ROWS;

    u32 base;
    asm("{ .reg .u64 a; cvta.to.shared.u64 a, %1; cvt.u32.u64 %0, a; }" : "=r"(base) : "l"(s));
    u32 in0_r, pB_r;
    asm("mapa.shared::cluster.u32 %0, %1, %2;" : "=r"(in0_r) : "r"(base + 200704), "r"(peer));
    asm("mapa.shared::cluster.u32 %0, %1, %2;" : "=r"(pB_r) : "r"(base + 211840), "r"(peer));

    // stage weights: L0 own tiles; L1 all tiles x own ks; head own block
    {
        const uint4* p0 = g_W0f + rank * 2304;
        for (int i = t; i < 2304; i += 256) sW0[i] = p0[i];
        for (int i = t; i < 4096; i += 256) {
            int tile = i >> 8, ksl = (i >> 5) & 7, lane = i & 31;
            sW1[i] = g_W1f[(tile * 16 + 8 * (int)rank + ksl) * 32 + lane];
        }
        const uint4* ph = g_Hf + rank * 6144;
        for (int i = t; i < 6144; i += 256) sHf[i] = ph[i];
    }
    sb0[t] = bb0[t];
    sb1[t] = bb1[t];
    for (int i = t; i < 384; i += 256) sbh[i] = g_bh[i];
    for (int i = t; i < ROWS * 168; i += 256) in0[i] = __float2half(0.f);
    __syncthreads();
    CLUSTER_SYNC();        // init visible cluster-wide
    CLUSTER_ARRIVE();      // seed h-phase for step 0
    if (t < 96) {          // x(0)
        int r = t / 12, f = t - r * 12;
        in0[r * 168 + f] = __float2half(g_x1[(bb + r) * S_ * F_ + f]);
    }

    const int ra2 = 2 * ti, rb2 = 2 * ti + 1;
    const int hb = 192 * (int)rank;
    const int gob = (8 * (int)rank + w) * 16;                  // L0 out base
    const int ko1 = 1 + 4 * (int)rank, kp1 = 1 + 4 * (int)peer; // L0 h ks

    for (int step = 0; step < S_; ++step) {
        __syncthreads();   // local in0 (x(s), own h(s-1)) visible

        // ======== L0: own 8 tiles, K=144 (x + own-h, [wait], peer-h) ========
        float dA[4], dB[4];
        {
            dA[0] = dA[1] = sb0[gob + gg];
            dA[2] = dA[3] = sb0[gob + gg + 8];
            dB[0] = dB[1] = dB[2] = dB[3] = 0.f;
            {
                u32 b0 = *(const u32*)&in0[gg * 168 + ti * 2];
                u32 b1 = *(const u32*)&in0[gg * 168 + ti * 2 + 8];
                mma16816(dA, sW0[(w * 9 + 0) * 32 + l], b0, b1);
            }
#pragma unroll
            for (int j = 0; j < 4; j++) {
                int ks = ko1 + j;
                u32 b0 = *(const u32*)&in0[gg * 168 + ks * 16 + ti * 2];
                u32 b1 = *(const u32*)&in0[gg * 168 + ks * 16 + ti * 2 + 8];
                mma16816((j & 1) ? dB : dA, sW0[(w * 9 + ks) * 32 + l], b0, b1);
            }
        }
        CLUSTER_WAIT();    // h(s-1) peer half landed
        {
#pragma unroll
            for (int j = 0; j < 4; j++) {
                int ks = kp1 + j;
                u32 b0 = *(const u32*)&in0[gg * 168 + ks * 16 + ti * 2];
                u32 b1 = *(const u32*)&in0[gg * 168 + ks * 16 + ti * 2 + 8];
                mma16816((j & 1) ? dA : dB, sW0[(w * 9 + ks) * 32 + l], b0, b1);
            }
            int i0 = ra2 * 264 + gob + gg, i1 = rb2 * 264 + gob + gg;
            za[i0]     = __float2half(siluf(dA[0] + dB[0]));
            za[i1]     = __float2half(siluf(dA[1] + dB[1]));
            za[i0 + 8] = __float2half(siluf(dA[2] + dB[2]));
            za[i1 + 8] = __float2half(siluf(dA[3] + dB[3]));
        }
        __syncthreads();   // za complete (local)

        // ======== L1 K-split: ALL 256 outs over own za half ========
        {
            const int t0 = 2 * w, t1 = 2 * w + 1;
            const int o0 = t0 * 16 + gg, o1 = t1 * 16 + gg;
            float d0[4], d1[4];
            d0[0] = d0[1] = d0[2] = d0[3] = 0.f;
            d1[0] = d1[1] = d1[2] = d1[3] = 0.f;
#pragma unroll
            for (int j = 0; j < 8; j++) {
                int ksg = 8 * (int)rank + j;
                u32 b0 = *(const u32*)&za[gg * 264 + ksg * 16 + ti * 2];
                u32 b1 = *(const u32*)&za[gg * 264 + ksg * 16 + ti * 2 + 8];
                mma16816(d0, sW1[(t0 * 8 + j) * 32 + l], b0, b1);
                mma16816(d1, sW1[(t1 * 8 + j) * 32 + l], b0, b1);
            }
            // own partial: local pA + remote pB (peer's pB buffer)
            int i0 = ra2 * 264 + o0, i1 = rb2 * 264 + o0;
            int i2 = ra2 * 264 + o1, i3 = rb2 * 264 + o1;
            __half v00 = __float2half(d0[0]), v01 = __float2half(d0[1]);
            __half v02 = __float2half(d0[2]), v03 = __float2half(d0[3]);
            __half v10 = __float2half(d1[0]), v11 = __float2half(d1[1]);
            __half v12 = __float2half(d1[2]), v13 = __float2half(d1[3]);
            pA[i0] = v00;     pA[i1] = v01;
            pA[i0 + 8] = v02; pA[i1 + 8] = v03;
            pA[i2] = v10;     pA[i3] = v11;
            pA[i2 + 8] = v12; pA[i3 + 8] = v13;
            sts_r16(pB_r + i0 * 2, v00);       sts_r16(pB_r + i1 * 2, v01);
            sts_r16(pB_r + (i0 + 8) * 2, v02); sts_r16(pB_r + (i1 + 8) * 2, v03);
            sts_r16(pB_r + i2 * 2, v10);       sts_r16(pB_r + i3 * 2, v11);
            sts_r16(pB_r + (i2 + 8) * 2, v12); sts_r16(pB_r + (i3 + 8) * 2, v13);
        }
        __syncthreads();   // local pA visible
        CLUSTER_ARRIVE();  // partial pushed (release)
        // prefetch x(s+1) while waiting
        float xreg = 0.f;
        if (t < 96 && step + 1 < S_) {
            int r = t / 12, f = t - r * 12;
            xreg = __ldg(&g_x1[((bb + r) * S_ + step + 1) * F_ + f]);
        }
        CLUSTER_WAIT();    // peer partial landed (acquire)

        // ======== zb = silu(pA + pB + b1), full 256, redundant on both CTAs ==
#pragma unroll
        for (int r = 0; r < ROWS; r++) {
            float v = __half2float(pA[r * 264 + t]) + __half2float(pB[r * 264 + t]) + sb1[t];
            zb[r * 264 + t] = __float2half(siluf(v));
        }
        __syncthreads();   // zb complete

        // ======== head: own 192 outs, full K=256, no waits ========
        {
            const bool two = (w < 4);
            const int lt0 = w, lt1 = 8 + w;
            float e0[4], e1[4];
            e0[0] = e0[1] = sbh[hb + lt0 * 16 + gg];
            e0[2] = e0[3] = sbh[hb + lt0 * 16 + gg + 8];
            if (two) {
                e1[0] = e1[1] = sbh[hb + lt1 * 16 + gg];
                e1[2] = e1[3] = sbh[hb + lt1 * 16 + gg + 8];
            } else {
                e1[0] = e1[1] = e1[2] = e1[3] = 0.f;
            }
#pragma unroll
            for (int ks = 0; ks < 16; ks++) {
                u32 b0 = *(const u32*)&zb[gg * 264 + ks * 16 + ti * 2];
                u32 b1 = *(const u32*)&zb[gg * 264 + ks * 16 + ti * 2 + 8];
                if (two) {
                    mma16816(e0, sHf[(lt0 * 16 + ks) * 32 + l], b0, b1);
                    mma16816(e1, sHf[(lt1 * 16 + ks) * 32 + l], b0, b1);
                } else {
                    mma16816((ks & 1) ? e1 : e0, sHf[(lt0 * 16 + ks) * 32 + l], b0, b1);
                }
            }
            if (two) {
                int ob0 = lt0 * 16, ob1 = lt1 * 16;
                hdro[ra2 * 200 + ob0 + gg] = e0[0];     hdro[rb2 * 200 + ob0 + gg] = e0[1];
                hdro[ra2 * 200 + ob0 + gg + 8] = e0[2]; hdro[rb2 * 200 + ob0 + gg + 8] = e0[3];
                hdro[ra2 * 200 + ob1 + gg] = e1[0];     hdro[rb2 * 200 + ob1 + gg] = e1[1];
                hdro[ra2 * 200 + ob1 + gg + 8] = e1[2]; hdro[rb2 * 200 + ob1 + gg + 8] = e1[3];
            } else {
                int ob = lt0 * 16;
                hdro[ra2 * 200 + ob + gg] = e0[0] + e1[0];
                hdro[rb2 * 200 + ob + gg] = e0[1] + e1[1];
                hdro[ra2 * 200 + ob + gg + 8] = e0[2] + e1[2];
                hdro[rb2 * 200 + ob + gg + 8] = e0[3] + e1[3];
            }
        }
        __syncthreads();   // hdro ready

        // ======== combine + feedback + h store ========
#pragma unroll
        for (int it = 0; it < 2; it++) {
            int i = t + 256 * it;
            int row = i >> 6, j = i & 63;
            float f1 = tanh_ap(hdro[row * 200 + j]);
            float f2 = tanh_ap(hdro[row * 200 + 64 + j]);
            float sg = sigf(hdro[row * 200 + 128 + j]);
            float h = f1 + sg * (f2 - f1);
            int jg = 64 * (int)rank + j;
            __half hh = __float2half(h);
            int idx = row * 168 + 16 + jg;
            in0[idx] = hh;
            sts_r16(in0_r + idx * 2, hh);
            g_hs[((bb + row) * S_ + step) * H_ + jg] = h;
        }
        if (step + 1 < S_) {
            CLUSTER_ARRIVE();   // h phase for next step (release: remote h stores)
            if (t < 96) {
                int r = t / 12, f = t - r * 12;
                in0[r * 168 + f] = __float2half(xreg);
            }
        }
    }
    CLUSTER_SYNC();   // drain
}

// ---------------- fused back ----------------
__global__ void k_back(const float* __restrict__ Wfc, const float* __restrict__ bfc,
                       float* __restrict__ out) {
    __shared__ float r1s[S_][4];
    int b = blockIdx.x, t = threadIdx.x;
    int w = t >> 5, lane = t & 31;
    for (int s = w; s < S_; s += 8) {
        const float* h = g_hs + (size_t)(b * S_ + s) * H_;
        float a0 = 0.f, a1 = 0.f, a2 = 0.f;
        for (int i = lane; i < H_; i += 32) {
            float hv = h[i];
            a0 = fmaf(hv, Wfc[i], a0);
            a1 = fmaf(hv, Wfc[H_ + i], a1);
            a2 = fmaf(hv, Wfc[2 * H_ + i], a2);
        }
#pragma unroll
        for (int o = 16; o; o >>= 1) {
            a0 += __shfl_xor_sync(0xffffffffu, a0, o);
            a1 += __shfl_xor_sync(0xffffffffu, a1, o);
            a2 += __shfl_xor_sync(0xffffffffu, a2, o);
        }
        if (!lane) {
            r1s[s][0] = a0 + bfc[0] + g_x3[(b * S_ + s) * 3 + 0];
            r1s[s][1] = a1 + bfc[1] + g_x3[(b * S_ + s) * 3 + 1];
            r1s[s][2] = a2 + bfc[2] + g_x3[(b * S_ + s) * 3 + 2];
        }
    }
    __syncthreads();
    if (t < S_) {
        float a0 = g_mean[b * F_ + 0] + g_x2[(b * S_ + t) * 3 + 0];
        float a1 = g_mean[b * F_ + 1] + g_x2[(b * S_ + t) * 3 + 1];
        float a2 = g_mean[b * F_ + 2] + g_x2[(b * S_ + t) * 3 + 2];
        for (int s = 0; s < S_; ++s) {
            a0 = fmaf(r1s[s][0], g_WfT[0 * S2_ + s * S_ + t], a0);
            a1 = fmaf(r1s[s][1], g_WfT[1 * S2_ + s * S_ + t], a1);
            a2 = fmaf(r1s[s][2], g_WfT[2 * S2_ + s * S_ + t], a2);
        }
        float* o = out + (b * S_ + t) * 3;
        o[0] = a0; o[1] = a1; o[2] = a2;
    }
}

// ---------------- launch ----------------
extern "C" void kernel_launch(void* const* d_in, const int* in_sizes, int n_in,
                              void* d_out, int out_size) {
    const float* x     = (const float*)d_in[0];
    const float* c3    = (const float*)d_in[1];
    const float* l3    = (const float*)d_in[2];
    const float* c6    = (const float*)d_in[3];
    const float* l6    = (const float*)d_in[4];
    const float* c12   = (const float*)d_in[5];
    const float* l12   = (const float*)d_in[6];
    const float* c24   = (const float*)d_in[7];
    const float* l24   = (const float*)d_in[8];
    const float* Wb0   = (const float*)d_in[9];
    const float* bb0   = (const float*)d_in[10];
    const float* Wb1   = (const float*)d_in[11];
    const float* bb1   = (const float*)d_in[12];
    const float* Wff1  = (const float*)d_in[13];
    const float* bff1  = (const float*)d_in[14];
    const float* Wff2  = (const float*)d_in[15];
    const float* bff2  = (const float*)d_in[16];
    const float* Wta   = (const float*)d_in[17];
    const float* bta   = (const float*)d_in[18];
    const float* Wtb   = (const float*)d_in[19];
    const float* btb   = (const float*)d_in[20];
    const float* Wfc   = (const float*)d_in[21];
    const float* bfc   = (const float*)d_in[22];
    const float* Wfits = (const float*)d_in[23];
    float* out = (float*)d_out;

    const int SMEM_RNN = 230272;
    cudaFuncSetAttribute(k_rnn, cudaFuncAttributeMaxDynamicSharedMemorySize, SMEM_RNN);

    const int NPRE = (16 * 9 * 32 + 16 * 16 * 32 + 24 * 16 * 32 + 384) + 6 * S2_;
    k_preall<<<(NPRE + 255) / 256, 256>>>(Wb0, Wb1, Wff1, Wff2, Wta, Wtb,
                                          bff1, bff2, bta, btb,
                                          c3, l3, c6, l6, c12, l12, c24, l24, Wfits);
    k_mean<<<(B_ * F_ * 32 + 255) / 256, 256>>>(x);
    k_front<<<B_, 192>>>(x);
    k_rnn<<<128, 256, SMEM_RNN>>>(bb0, bb1);
    k_back<<<B_, 256>>>(Wfc, bfc, out);
}

// round 12
// speedup vs baseline: 1.3905x; 1.1259x over previous
#include <cuda_runtime.h>
#include <cuda_fp16.h>

#define B_ 512
#define S_ 168
#define F_ 12
#define H_ 128
#define O_ 3
#define S2_ (S_ * S_)
#define ROWS 8

typedef unsigned int u32;

// ---------------- device scratch ----------------
__device__ uint4 g_W0f[16 * 9 * 32];    // L0 fragments [tile][ks][lane] (K=144: x|pad|h)
__device__ uint4 g_W1f[16 * 16 * 32];   // L1 fragments [tile][ks][lane]
__device__ uint4 g_Hf[24 * 16 * 32];    // head fragments (per-rank blocks [ff1|ff2|gate])
__device__ float g_bh[384];
__device__ float g_T[3 * S2_];
__device__ float g_WfT[3 * S2_];
__device__ float g_mean[B_ * F_];
__device__ float g_x1[B_ * S_ * F_];
__device__ float g_x2[B_ * S_ * O_];
__device__ float g_x3[B_ * S_ * O_];
__device__ float g_hs[B_ * S_ * H_];

// ---------------- helpers ----------------
__device__ __forceinline__ float tanh_ap(float x) {
    float y;
    asm("tanh.approx.f32 %0, %1;" : "=f"(y) : "f"(x));
    return y;
}
__device__ __forceinline__ float siluf(float x) {
    return x * fmaf(0.5f, tanh_ap(0.5f * x), 0.5f);
}
__device__ __forceinline__ float sigf(float x) {
    return fmaf(0.5f, tanh_ap(0.5f * x), 0.5f);
}
__device__ __forceinline__ u32 hpack(float a, float b) {
    __half2 h = __floats2half2_rn(a, b);
    return *reinterpret_cast<u32*>(&h);
}
__device__ __forceinline__ void mma16816(float* d, uint4 A, u32 b0, u32 b1) {
    asm volatile(
        "mma.sync.aligned.m16n8k16.row.col.f32.f16.f16.f32 "
        "{%0,%1,%2,%3},{%4,%5,%6,%7},{%8,%9},{%0,%1,%2,%3};"
        : "+f"(d[0]), "+f"(d[1]), "+f"(d[2]), "+f"(d[3])
        : "r"(A.x), "r"(A.y), "r"(A.z), "r"(A.w), "r"(b0), "r"(b1));
}
#define CLUSTER_SYNC() do { \
    asm volatile("barrier.cluster.arrive.aligned;" ::: "memory"); \
    asm volatile("barrier.cluster.wait.aligned;" ::: "memory"); } while (0)
#define CLUSTER_ARRIVE() asm volatile("barrier.cluster.arrive.aligned;" ::: "memory")
#define CLUSTER_WAIT()   asm volatile("barrier.cluster.wait.aligned;" ::: "memory")

__device__ __forceinline__ void sts_r32(u32 a, u32 v) {
    asm volatile("st.shared::cluster.b32 [%0], %1;" :: "r"(a), "r"(v));
}

// weight element accessors
// L0 K layout: [0,12)=x, [12,16)=pad, [16,144)=h
__device__ __forceinline__ float w0_at(const float* W, int o, int k) {
    if (k < 12)  return W[o * 140 + k];
    if (k < 16)  return 0.f;
    return W[o * 140 + (k - 4)];
}
// head reorder: block r (192 rows) = [ff1(64r:64r+64); ff2(...); gate(...)]
__device__ __forceinline__ float wh_at(const float* f1, const float* f2,
                                       const float* ta, const float* tb, int m, int k) {
    int blk = m / 192, o = m % 192, base = blk * 64;
    if (o < 64)  return f1[(base + o) * 256 + k];
    if (o < 128) return f2[(base + o - 64) * 256 + k];
    return ta[(base + o - 128) * 256 + k] + tb[(base + o - 128) * 256 + k];
}

__device__ __forceinline__ float sff_contrib(const float* __restrict__ conv,
                                             const float* __restrict__ lin,
                                             int p, int seg, int pad, int so, int si) {
    int phase = so % p, q = so / p;
    float acc = 0.f;
    for (int kk = 0; kk < seg; ++kk) {
        int d = si - (kk * p + phase);
        float c = 0.f;
        if (d >= -pad && d <= pad) c = conv[d + pad];
        if (d == 0) c += 1.f;
        acc += lin[q * seg + kk] * c;
    }
    return acc;
}

// ---------------- merged prep: fragments + biases + T + WfT ----------------
__global__ void k_preall(const float* __restrict__ Wb0, const float* __restrict__ Wb1,
                         const float* __restrict__ Wff1, const float* __restrict__ Wff2,
                         const float* __restrict__ Wta, const float* __restrict__ Wtb,
                         const float* __restrict__ bff1, const float* __restrict__ bff2,
                         const float* __restrict__ bta, const float* __restrict__ btb,
                         const float* __restrict__ c3, const float* __restrict__ l3,
                         const float* __restrict__ c6, const float* __restrict__ l6,
                         const float* __restrict__ c12, const float* __restrict__ l12,
                         const float* __restrict__ c24, const float* __restrict__ l24,
                         const float* __restrict__ Wfits) {
    int idx = blockIdx.x * blockDim.x + threadIdx.x;
    const int N0 = 16 * 9 * 32, N1 = 16 * 16 * 32, NH = 24 * 16 * 32;
    const int NP = N0 + N1 + NH + 384;
    if (idx < N0 + N1 + NH) {
        int which, tile, ks, l, i = idx;
        if (i < N0)           { which = 0; tile = i / (9 * 32);  ks = (i / 32) % 9; }
        else if (i < N0 + N1) { which = 1; i -= N0; tile = i / (16 * 32); ks = (i / 32) % 16; }
        else                  { which = 2; i -= N0 + N1; tile = i / (16 * 32); ks = (i / 32) % 16; }
        l = i % 32;
        int g = l / 4, ti = l % 4;
        int r0 = tile * 16 + g, k0 = ks * 16 + ti * 2;
        float e[4][2];
        for (int half = 0; half < 2; half++) {
            for (int rr = 0; rr < 2; rr++) {
                for (int cc = 0; cc < 2; cc++) {
                    int o = r0 + rr * 8, k = k0 + half * 8 + cc;
                    float wv;
                    if (which == 0)      wv = w0_at(Wb0, o, k);
                    else if (which == 1) wv = Wb1[o * 256 + k];
                    else                 wv = wh_at(Wff1, Wff2, Wta, Wtb, o, k);
                    e[half * 2 + rr][cc] = wv;
                }
            }
        }
        uint4 out;
        out.x = hpack(e[0][0], e[0][1]);
        out.y = hpack(e[1][0], e[1][1]);
        out.z = hpack(e[2][0], e[2][1]);
        out.w = hpack(e[3][0], e[3][1]);
        if (which == 0)      g_W0f[idx] = out;
        else if (which == 1) g_W1f[idx - N0] = out;
        else                 g_Hf[idx - N0 - N1] = out;
    } else if (idx < NP) {
        int m = idx - N0 - N1 - NH;
        int blk = m / 192, o = m % 192, base = blk * 64;
        float b;
        if (o < 64)       b = bff1[base + o];
        else if (o < 128) b = bff2[base + o - 64];
        else              b = bta[base + o - 128] + btb[base + o - 128];
        g_bh[m] = b;
    } else if (idx < NP + 3 * S2_) {
        int j = idx - NP;
        int L = j / S2_, r = j % S2_;
        int so = r / S_, si = r % S_;
        float a = sff_contrib(c3 + L * 3, l3 + L * 56 * 56, 3, 56, 1, so, si)
                + sff_contrib(c6 + L * 7, l6 + L * 28 * 28, 6, 28, 3, so, si)
                + sff_contrib(c12 + L * 13, l12 + L * 14 * 14, 12, 14, 6, so, si)
                + sff_contrib(c24 + L * 25, l24 + L * 7 * 7, 24, 7, 12, so, si);
        g_T[L * S2_ + si * S_ + so] = 0.25f * a;
    } else if (idx < NP + 6 * S2_) {
        int j = idx - NP - 3 * S2_;
        int c = j / S2_, r = j % S2_;
        int s = r / S_, p = r % S_;
        g_WfT[c * S2_ + s * S_ + p] = Wfits[c * S2_ + p * S_ + s];
    }
}

__global__ void k_mean(const float* __restrict__ x) {
    int w = (blockIdx.x * blockDim.x + threadIdx.x) >> 5;
    int lane = threadIdx.x & 31;
    if (w >= B_ * F_) return;
    const float* p = x + w * S_;
    float s = 0.f;
    for (int i = lane; i < S_; i += 32) s += p[i];
#pragma unroll
    for (int o = 16; o; o >>= 1) s += __shfl_xor_sync(0xffffffffu, s, o);
    if (!lane) g_mean[w] = s * (1.f / (float)S_);
}

// ---------------- fused front ----------------
__global__ void k_front(const float* __restrict__ x) {
    __shared__ float xs[S_][F_];
    __shared__ float x1s[S_][4];
    int b = blockIdx.x, t = threadIdx.x;
    for (int i = t; i < S_ * F_; i += blockDim.x) {
        int si = i / F_, f = i % F_;
        xs[si][f] = x[b * F_ * S_ + f * S_ + si] - g_mean[b * F_ + f];
    }
    __syncthreads();
    if (t < S_) {
        float acc[F_];
#pragma unroll
        for (int f = 0; f < F_; f++) acc[f] = 0.f;
        for (int si = 0; si < S_; ++si) {
            float tw = g_T[si * S_ + t];
#pragma unroll
            for (int f = 0; f < F_; f++) acc[f] = fmaf(tw, xs[si][f], acc[f]);
        }
        float* o = g_x1 + (b * S_ + t) * F_;
#pragma unroll
        for (int f = 0; f < F_; f++) o[f] = acc[f];
        x1s[t][0] = acc[0]; x1s[t][1] = acc[1]; x1s[t][2] = acc[2];
    }
    __syncthreads();
    if (t < S_) {
        float a2[3] = {0.f, 0.f, 0.f}, a3[3] = {0.f, 0.f, 0.f};
        for (int si = 0; si < S_; ++si) {
            float t1 = g_T[S2_ + si * S_ + t];
            float t2 = g_T[2 * S2_ + si * S_ + t];
#pragma unroll
            for (int c = 0; c < 3; c++) {
                a2[c] = fmaf(t1, x1s[si][c], a2[c]);
                a3[c] = fmaf(t2, x1s[si][c], a3[c]);
            }
        }
#pragma unroll
        for (int c = 0; c < 3; c++) {
            g_x2[(b * S_ + t) * 3 + c] = a2[c];
            g_x3[(b * S_ + t) * 3 + c] = a3[c];
        }
    }
}

// ---------------- CfC recurrence: cluster-2, K-split L1, tightened ----------
// SMEM (bytes):
//   [0,36864)         sW0  (this CTA's 8 L0 tiles)
//   [36864,102400)    sW1  (ALL 16 tiles x own 8 ks)
//   [102400,200704)   sHf  (this CTA's 12 head tiles)
//   [200704,203392)   in0  [8][168]h
//   [203392,207616)   za   [8][264]h
//   [207616,211712)   pB   COL-MAJOR [256 cols][8 rows] half (peer partial)
//   [211712,215936)   zb   [8][264]h
//   [215936,222336)   hdro [8][200]f
__global__ void __launch_bounds__(256, 1) __cluster_dims__(2, 1, 1)
k_rnn(const float* __restrict__ bb0, const float* __restrict__ bb1) {
    extern __shared__ __align__(16) char s[];
    uint4*  sW0  = (uint4*)(s);
    uint4*  sW1  = (uint4*)(s + 36864);
    uint4*  sHf  = (uint4*)(s + 102400);
    __half* in0  = (__half*)(s + 200704);
    __half* za   = (__half*)(s + 203392);
    char*   pB   = (char*)(s + 207616);
    __half* zb   = (__half*)(s + 211712);
    float*  hdro = (float*)(s + 215936);

    const int t = threadIdx.x, w = t >> 5, l = t & 31, gg = l >> 2, ti = l & 3;
    u32 rank;
    asm("mov.u32 %0, %%cluster_ctarank;" : "=r"(rank));
    const u32 peer = rank ^ 1u;
    const int bb = (blockIdx.x >> 1) * ROWS;

    u32 base;
    asm("{ .reg .u64 a; cvta.to.shared.u64 a, %1; cvt.u32.u64 %0, a; }" : "=r"(base) : "l"(s));
    u32 in0_r, pB_r;
    asm("mapa.shared::cluster.u32 %0, %1, %2;" : "=r"(in0_r) : "r"(base + 200704), "r"(peer));
    asm("mapa.shared::cluster.u32 %0, %1, %2;" : "=r"(pB_r) : "r"(base + 207616), "r"(peer));

    // stage weights: L0 own tiles; L1 all tiles x own ks; head own block
    {
        const uint4* p0 = g_W0f + rank * 2304;
        for (int i = t; i < 2304; i += 256) sW0[i] = p0[i];
        for (int i = t; i < 4096; i += 256) {
            int tile = i >> 8, ksl = (i >> 5) & 7, lane = i & 31;
            sW1[i] = g_W1f[(tile * 16 + 8 * (int)rank + ksl) * 32 + lane];
        }
        const uint4* ph = g_Hf + rank * 6144;
        for (int i = t; i < 6144; i += 256) sHf[i] = ph[i];
    }
    for (int i = t; i < ROWS * 168; i += 256) in0[i] = __float2half(0.f);
    __syncthreads();
    CLUSTER_SYNC();        // zeroed h region visible cluster-wide
    CLUSTER_ARRIVE();      // seed h-phase for step 0
    if (t < 96) {          // x(0)
        int r = t / 12, f = t - r * 12;
        in0[r * 168 + f] = __float2half(g_x1[(bb + r) * S_ * F_ + f]);
    }

    const int ra2 = 2 * ti, rb2 = 2 * ti + 1;
    const int hb = 192 * (int)rank;
    const int gob = (8 * (int)rank + w) * 16;
    const int ko1 = 1 + 4 * (int)rank, kp1 = 1 + 4 * (int)peer;
    const int t0 = 2 * w, t1 = 2 * w + 1;
    const int o0 = t0 * 16 + gg, o1 = t1 * 16 + gg;
    const bool two = (w < 4);
    const int lt0 = w, lt1 = 8 + w;

    // bias preloads (registers; fixed per thread)
    const float rb0a = bb0[gob + gg], rb0b = bb0[gob + gg + 8];
    const float rb1c0 = bb1[o0],  rb1c1 = bb1[o0 + 8];
    const float rb1c2 = bb1[o1],  rb1c3 = bb1[o1 + 8];
    const float he0a = g_bh[hb + lt0 * 16 + gg];
    const float he0b = g_bh[hb + lt0 * 16 + gg + 8];
    const float he1a = two ? g_bh[hb + lt1 * 16 + gg] : 0.f;
    const float he1b = two ? g_bh[hb + lt1 * 16 + gg + 8] : 0.f;

    for (int step = 0; step < S_; ++step) {
        __syncthreads();   // local in0 (x(s), own h(s-1)) visible

        // ======== L0: own 8 tiles, K=144 (x + own-h, [wait], peer-h) ========
        float dA[4], dB[4];
        {
            dA[0] = dA[1] = rb0a;
            dA[2] = dA[3] = rb0b;
            dB[0] = dB[1] = dB[2] = dB[3] = 0.f;
            {
                u32 b0 = *(const u32*)&in0[gg * 168 + ti * 2];
                u32 b1 = *(const u32*)&in0[gg * 168 + ti * 2 + 8];
                mma16816(dA, sW0[(w * 9 + 0) * 32 + l], b0, b1);
            }
#pragma unroll
            for (int j = 0; j < 4; j++) {
                int ks = ko1 + j;
                u32 b0 = *(const u32*)&in0[gg * 168 + ks * 16 + ti * 2];
                u32 b1 = *(const u32*)&in0[gg * 168 + ks * 16 + ti * 2 + 8];
                mma16816((j & 1) ? dB : dA, sW0[(w * 9 + ks) * 32 + l], b0, b1);
            }
        }
        CLUSTER_WAIT();    // h(s-1) peer half landed
        {
#pragma unroll
            for (int j = 0; j < 4; j++) {
                int ks = kp1 + j;
                u32 b0 = *(const u32*)&in0[gg * 168 + ks * 16 + ti * 2];
                u32 b1 = *(const u32*)&in0[gg * 168 + ks * 16 + ti * 2 + 8];
                mma16816((j & 1) ? dA : dB, sW0[(w * 9 + ks) * 32 + l], b0, b1);
            }
            int i0 = ra2 * 264 + gob + gg, i1 = rb2 * 264 + gob + gg;
            za[i0]     = __float2half(siluf(dA[0] + dB[0]));
            za[i1]     = __float2half(siluf(dA[1] + dB[1]));
            za[i0 + 8] = __float2half(siluf(dA[2] + dB[2]));
            za[i1 + 8] = __float2half(siluf(dA[3] + dB[3]));
        }
        __syncthreads();   // za complete (local)

        // ======== L1 K-split: ALL 256 outs over own za half (4 chains) ======
        float d0[4], d1[4];
        {
            float d0a[4] = {0.f, 0.f, 0.f, 0.f}, d0b[4] = {0.f, 0.f, 0.f, 0.f};
            float d1a[4] = {0.f, 0.f, 0.f, 0.f}, d1b[4] = {0.f, 0.f, 0.f, 0.f};
#pragma unroll
            for (int j = 0; j < 8; j++) {
                int ksg = 8 * (int)rank + j;
                u32 b0 = *(const u32*)&za[gg * 264 + ksg * 16 + ti * 2];
                u32 b1 = *(const u32*)&za[gg * 264 + ksg * 16 + ti * 2 + 8];
                mma16816((j & 1) ? d0b : d0a, sW1[(t0 * 8 + j) * 32 + l], b0, b1);
                mma16816((j & 1) ? d1b : d1a, sW1[(t1 * 8 + j) * 32 + l], b0, b1);
            }
#pragma unroll
            for (int j = 0; j < 4; j++) {
                d0[j] = d0a[j] + d0b[j];
                d1[j] = d1a[j] + d1b[j];
            }
            // push own partial to peer's pB (col-major: 4 x 32-bit remote stores)
            sts_r32(pB_r + o0 * 16 + ti * 4,       hpack(d0[0], d0[1]));
            sts_r32(pB_r + (o0 + 8) * 16 + ti * 4, hpack(d0[2], d0[3]));
            sts_r32(pB_r + o1 * 16 + ti * 4,       hpack(d1[0], d1[1]));
            sts_r32(pB_r + (o1 + 8) * 16 + ti * 4, hpack(d1[2], d1[3]));
        }
        CLUSTER_ARRIVE();  // partial pushed (release)
        float xreg = 0.f;
        if (t < 96 && step + 1 < S_) {
            int r = t / 12, f = t - r * 12;
            xreg = __ldg(&g_x1[((bb + r) * S_ + step + 1) * F_ + f]);
        }
        CLUSTER_WAIT();    // peer partial landed (acquire)

        // ======== zb fuse: regs + pB + bias, fragment layout ========
        {
            float2 q;
            q = __half22float2(*(const __half2*)(pB + o0 * 16 + ti * 4));
            zb[ra2 * 264 + o0] = __float2half(siluf(d0[0] + q.x + rb1c0));
            zb[rb2 * 264 + o0] = __float2half(siluf(d0[1] + q.y + rb1c0));
            q = __half22float2(*(const __half2*)(pB + (o0 + 8) * 16 + ti * 4));
            zb[ra2 * 264 + o0 + 8] = __float2half(siluf(d0[2] + q.x + rb1c1));
            zb[rb2 * 264 + o0 + 8] = __float2half(siluf(d0[3] + q.y + rb1c1));
            q = __half22float2(*(const __half2*)(pB + o1 * 16 + ti * 4));
            zb[ra2 * 264 + o1] = __float2half(siluf(d1[0] + q.x + rb1c2));
            zb[rb2 * 264 + o1] = __float2half(siluf(d1[1] + q.y + rb1c2));
            q = __half22float2(*(const __half2*)(pB + (o1 + 8) * 16 + ti * 4));
            zb[ra2 * 264 + o1 + 8] = __float2half(siluf(d1[2] + q.x + rb1c3));
            zb[rb2 * 264 + o1 + 8] = __float2half(siluf(d1[3] + q.y + rb1c3));
        }
        __syncthreads();   // zb complete

        // ======== head: own 192 outs, full K=256, dual chains, no waits =====
        {
            float e0a[4], e0b[4], e1a[4], e1b[4];
            e0a[0] = e0a[1] = he0a;
            e0a[2] = e0a[3] = he0b;
            e1a[0] = e1a[1] = he1a;
            e1a[2] = e1a[3] = he1b;
#pragma unroll
            for (int j = 0; j < 4; j++) { e0b[j] = 0.f; e1b[j] = 0.f; }
#pragma unroll
            for (int ks = 0; ks < 16; ks++) {
                u32 b0 = *(const u32*)&zb[gg * 264 + ks * 16 + ti * 2];
                u32 b1 = *(const u32*)&zb[gg * 264 + ks * 16 + ti * 2 + 8];
                mma16816((ks & 1) ? e0b : e0a, sHf[(lt0 * 16 + ks) * 32 + l], b0, b1);
                if (two)
                    mma16816((ks & 1) ? e1b : e1a, sHf[(lt1 * 16 + ks) * 32 + l], b0, b1);
            }
            int ob0 = lt0 * 16;
            hdro[ra2 * 200 + ob0 + gg]     = e0a[0] + e0b[0];
            hdro[rb2 * 200 + ob0 + gg]     = e0a[1] + e0b[1];
            hdro[ra2 * 200 + ob0 + gg + 8] = e0a[2] + e0b[2];
            hdro[rb2 * 200 + ob0 + gg + 8] = e0a[3] + e0b[3];
            if (two) {
                int ob1 = lt1 * 16;
                hdro[ra2 * 200 + ob1 + gg]     = e1a[0] + e1b[0];
                hdro[rb2 * 200 + ob1 + gg]     = e1a[1] + e1b[1];
                hdro[ra2 * 200 + ob1 + gg + 8] = e1a[2] + e1b[2];
                hdro[rb2 * 200 + ob1 + gg + 8] = e1a[3] + e1b[3];
            }
        }
        __syncthreads();   // hdro ready

        // ======== combine (packed): thread -> (row, 2 adjacent j) ========
        {
            int row = t >> 5, j0 = (t & 31) * 2;
            float2 v1 = *(const float2*)&hdro[row * 200 + j0];
            float2 v2 = *(const float2*)&hdro[row * 200 + 64 + j0];
            float2 vg = *(const float2*)&hdro[row * 200 + 128 + j0];
            float f1x = tanh_ap(v1.x), f2x = tanh_ap(v2.x), sgx = sigf(vg.x);
            float f1y = tanh_ap(v1.y), f2y = tanh_ap(v2.y), sgy = sigf(vg.y);
            float h0 = f1x + sgx * (f2x - f1x);
            float h1 = f1y + sgy * (f2y - f1y);
            int jg = 64 * (int)rank + j0;
            int idx = row * 168 + 16 + jg;
            u32 hh = hpack(h0, h1);
            *(u32*)&in0[idx] = hh;
            sts_r32(in0_r + idx * 2, hh);
            *(float2*)&g_hs[((size_t)(bb + row) * S_ + step) * H_ + jg] =
                make_float2(h0, h1);
        }
        if (step + 1 < S_) {
            CLUSTER_ARRIVE();   // h phase for next step (release)
            if (t < 96) {
                int r = t / 12, f = t - r * 12;
                in0[r * 168 + f] = __float2half(xreg);
            }
        }
    }
    CLUSTER_SYNC();   // drain
}

// ---------------- fused back ----------------
__global__ void k_back(const float* __restrict__ Wfc, const float* __restrict__ bfc,
                       float* __restrict__ out) {
    __shared__ float r1s[S_][4];
    int b = blockIdx.x, t = threadIdx.x;
    int w = t >> 5, lane = t & 31;
    for (int s = w; s < S_; s += 8) {
        const float* h = g_hs + (size_t)(b * S_ + s) * H_;
        float a0 = 0.f, a1 = 0.f, a2 = 0.f;
        for (int i = lane; i < H_; i += 32) {
            float hv = h[i];
            a0 = fmaf(hv, Wfc[i], a0);
            a1 = fmaf(hv, Wfc[H_ + i], a1);
            a2 = fmaf(hv, Wfc[2 * H_ + i], a2);
        }
#pragma unroll
        for (int o = 16; o; o >>= 1) {
            a0 += __shfl_xor_sync(0xffffffffu, a0, o);
            a1 += __shfl_xor_sync(0xffffffffu, a1, o);
            a2 += __shfl_xor_sync(0xffffffffu, a2, o);
        }
        if (!lane) {
            r1s[s][0] = a0 + bfc[0] + g_x3[(b * S_ + s) * 3 + 0];
            r1s[s][1] = a1 + bfc[1] + g_x3[(b * S_ + s) * 3 + 1];
            r1s[s][2] = a2 + bfc[2] + g_x3[(b * S_ + s) * 3 + 2];
        }
    }
    __syncthreads();
    if (t < S_) {
        float a0 = g_mean[b * F_ + 0] + g_x2[(b * S_ + t) * 3 + 0];
        float a1 = g_mean[b * F_ + 1] + g_x2[(b * S_ + t) * 3 + 1];
        float a2 = g_mean[b * F_ + 2] + g_x2[(b * S_ + t) * 3 + 2];
        for (int s = 0; s < S_; ++s) {
            a0 = fmaf(r1s[s][0], g_WfT[0 * S2_ + s * S_ + t], a0);
            a1 = fmaf(r1s[s][1], g_WfT[1 * S2_ + s * S_ + t], a1);
            a2 = fmaf(r1s[s][2], g_WfT[2 * S2_ + s * S_ + t], a2);
        }
        float* o = out + (b * S_ + t) * 3;
        o[0] = a0; o[1] = a1; o[2] = a2;
    }
}

// ---------------- launch ----------------
extern "C" void kernel_launch(void* const* d_in, const int* in_sizes, int n_in,
                              void* d_out, int out_size) {
    const float* x     = (const float*)d_in[0];
    const float* c3    = (const float*)d_in[1];
    const float* l3    = (const float*)d_in[2];
    const float* c6    = (const float*)d_in[3];
    const float* l6    = (const float*)d_in[4];
    const float* c12   = (const float*)d_in[5];
    const float* l12   = (const float*)d_in[6];
    const float* c24   = (const float*)d_in[7];
    const float* l24   = (const float*)d_in[8];
    const float* Wb0   = (const float*)d_in[9];
    const float* bb0   = (const float*)d_in[10];
    const float* Wb1   = (const float*)d_in[11];
    const float* bb1   = (const float*)d_in[12];
    const float* Wff1  = (const float*)d_in[13];
    const float* bff1  = (const float*)d_in[14];
    const float* Wff2  = (const float*)d_in[15];
    const float* bff2  = (const float*)d_in[16];
    const float* Wta   = (const float*)d_in[17];
    const float* bta   = (const float*)d_in[18];
    const float* Wtb   = (const float*)d_in[19];
    const float* btb   = (const float*)d_in[20];
    const float* Wfc   = (const float*)d_in[21];
    const float* bfc   = (const float*)d_in[22];
    const float* Wfits = (const float*)d_in[23];
    float* out = (float*)d_out;

    const int SMEM_RNN = 222336;
    cudaFuncSetAttribute(k_rnn, cudaFuncAttributeMaxDynamicSharedMemorySize, SMEM_RNN);

    const int NPRE = (16 * 9 * 32 + 16 * 16 * 32 + 24 * 16 * 32 + 384) + 6 * S2_;
    k_preall<<<(NPRE + 255) / 256, 256>>>(Wb0, Wb1, Wff1, Wff2, Wta, Wtb,
                                          bff1, bff2, bta, btb,
                                          c3, l3, c6, l6, c12, l12, c24, l24, Wfits);
    k_mean<<<(B_ * F_ * 32 + 255) / 256, 256>>>(x);
    k_front<<<B_, 192>>>(x);
    k_rnn<<<128, 256, SMEM_RNN>>>(bb0, bb1);
    k_back<<<B_, 256>>>(Wfc, bfc, out);
}